// round 1
// baseline (speedup 1.0000x reference)
#include <cuda_runtime.h>
#include <cstdint>

#define S_LEN 2048
#define DIMM  2048
#define NH    16
#define NKV   8
#define HD    128
#define NTOK  4096
#define QKV_OUT 4096
#define BQ    64
#define BKT   64
#define FL_SMEM_FLOATS (2*128*68 + 64*132 + 64*68 + 3*64)
#define FL_SMEM_BYTES  (FL_SMEM_FLOATS * 4)

// ---------------- scratch (static device memory; no allocation) ----------------
__device__ float g_qkv[(size_t)NTOK * QKV_OUT];   // 64 MB
__device__ float g_q[(size_t)NTOK * NH * HD];     // 32 MB
__device__ float g_k[(size_t)NTOK * NKV * HD];    // 16 MB
__device__ float g_attn[(size_t)NTOK * DIMM];     // 32 MB

// ---------------- SGEMM: C[M,N] = A[M,K] * B[N,K]^T (both row-major, K-contig) ----------------
__global__ __launch_bounds__(256) void sgemm_nt(
    const float* __restrict__ A, const float* __restrict__ B,
    float* __restrict__ C, int M, int N, int K)
{
    __shared__ float As[8][128];
    __shared__ float Bs[8][128];
    const int tid  = threadIdx.x;
    const int tx   = tid & 15, ty = tid >> 4;
    const int lrow = tid >> 1, lk = (tid & 1) << 2;
    const float* Ag = A + (size_t)(blockIdx.y * 128 + lrow) * K + lk;
    const float* Bg = B + (size_t)(blockIdx.x * 128 + lrow) * K + lk;

    float acc[8][8] = {};
    for (int k0 = 0; k0 < K; k0 += 8) {
        float4 a = *(const float4*)(Ag + k0);
        float4 b = *(const float4*)(Bg + k0);
        __syncthreads();
        As[lk+0][lrow] = a.x; As[lk+1][lrow] = a.y;
        As[lk+2][lrow] = a.z; As[lk+3][lrow] = a.w;
        Bs[lk+0][lrow] = b.x; Bs[lk+1][lrow] = b.y;
        Bs[lk+2][lrow] = b.z; Bs[lk+3][lrow] = b.w;
        __syncthreads();
        #pragma unroll
        for (int kk = 0; kk < 8; kk++) {
            float4 a0 = *(const float4*)&As[kk][ty*8];
            float4 a1 = *(const float4*)&As[kk][ty*8+4];
            float4 b0 = *(const float4*)&Bs[kk][tx*8];
            float4 b1 = *(const float4*)&Bs[kk][tx*8+4];
            float ra[8] = {a0.x,a0.y,a0.z,a0.w,a1.x,a1.y,a1.z,a1.w};
            float rb[8] = {b0.x,b0.y,b0.z,b0.w,b1.x,b1.y,b1.z,b1.w};
            #pragma unroll
            for (int i = 0; i < 8; i++)
                #pragma unroll
                for (int j = 0; j < 8; j++)
                    acc[i][j] += ra[i] * rb[j];
        }
    }
    #pragma unroll
    for (int i = 0; i < 8; i++) {
        float* cp = C + (size_t)(blockIdx.y*128 + ty*8 + i) * N + blockIdx.x*128 + tx*8;
        *(float4*)cp       = make_float4(acc[i][0],acc[i][1],acc[i][2],acc[i][3]);
        *(float4*)(cp + 4) = make_float4(acc[i][4],acc[i][5],acc[i][6],acc[i][7]);
    }
}

// ---------------- fused per-head RMSNorm + RoPE ----------------
// grid (NTOK, NH+NKV), block 128. Reads g_qkv, writes g_q / g_k.
__global__ __launch_bounds__(128) void norm_rope_kernel(
    const float* __restrict__ freqs,  // [S,1,64,2,2]
    const float* __restrict__ qw, const float* __restrict__ kw)
{
    const int t  = blockIdx.x;
    const int hh = blockIdx.y;
    const int d  = threadIdx.x;
    const bool isq = hh < NH;
    const int h = isq ? hh : hh - NH;
    const size_t base = (size_t)t * QKV_OUT + (isq ? h*HD : NH*HD + h*HD);
    float v = g_qkv[base + d];

    float ss = v * v;
    #pragma unroll
    for (int o = 16; o; o >>= 1) ss += __shfl_xor_sync(0xffffffffu, ss, o);
    __shared__ float red[4];
    if ((d & 31) == 0) red[d >> 5] = ss;
    __syncthreads();
    ss = red[0] + red[1] + red[2] + red[3];

    float w  = isq ? qw[d] : kw[d];
    float xn = v * rsqrtf(ss * (1.0f / HD) + 1e-5f) * w;

    float other = __shfl_xor_sync(0xffffffffu, xn, 1);
    int f = d >> 1, r = d & 1;
    float x0 = (r == 0) ? xn : other;
    float x1 = (r == 0) ? other : xn;
    int s = t & (S_LEN - 1);
    const float* fc = freqs + ((size_t)s * 64 + f) * 4 + r * 2;
    float outv = fc[0] * x0 + fc[1] * x1;

    if (isq) g_q[((size_t)t * NH  + h) * HD + d] = outv;
    else     g_k[((size_t)t * NKV + h) * HD + d] = outv;
}

// ---------------- fp32 flash attention ----------------
// grid (S/BQ, NH, B), 256 threads, dynamic smem.
__global__ __launch_bounds__(256) void flash_kernel(const float* __restrict__ mask)
{
    extern __shared__ float sm[];
    float* Qs  = sm;                 // [128 d][68]  (row index 0..63)
    float* Ks  = sm + 128*68;        // [128 d][68]
    float* Vs  = sm + 2*128*68;      // [64 key][132]
    float* Ps  = Vs + 64*132;        // [64 col][68 row]
    float* m_s = Ps + 64*68;
    float* l_s = m_s + 64;
    float* a_s = l_s + 64;

    const int tid  = threadIdx.x;
    const int lane = tid & 31, w = tid >> 5;
    const int tx = tid & 15, ty = tid >> 4;
    const int h = blockIdx.y, b = blockIdx.z;
    const int hkv = h >> 1;
    const int q0 = blockIdx.x * BQ;
    const int tok0 = b * S_LEN;
    const float scale = 0.088388347762f;   // 1/sqrt(128)

    // transpose-load Q tile -> Qs[d][row]; lane==row makes smem writes conflict-free
    {
        int n  = lane + ((w & 1) << 5);
        int qb = (w >> 1) * 8;
        const float* qr = g_q + ((size_t)(tok0 + q0 + n) * NH + h) * HD;
        #pragma unroll
        for (int i = 0; i < 8; i++) {
            int d0 = (qb + i) * 4;
            float4 v = *(const float4*)(qr + d0);
            Qs[(d0+0)*68 + n] = v.x;
            Qs[(d0+1)*68 + n] = v.y;
            Qs[(d0+2)*68 + n] = v.z;
            Qs[(d0+3)*68 + n] = v.w;
        }
    }
    if (tid < BQ) { m_s[tid] = -1e30f; l_s[tid] = 0.f; }
    float acc[4][8] = {};

    for (int kt = 0; kt < S_LEN; kt += BKT) {
        __syncthreads();
        // K tile transposed, V tile natural
        {
            int n  = lane + ((w & 1) << 5);
            int qb = (w >> 1) * 8;
            const float* kr = g_k + ((size_t)(tok0 + kt + n) * NKV + hkv) * HD;
            #pragma unroll
            for (int i = 0; i < 8; i++) {
                int d0 = (qb + i) * 4;
                float4 v = *(const float4*)(kr + d0);
                Ks[(d0+0)*68 + n] = v.x;
                Ks[(d0+1)*68 + n] = v.y;
                Ks[(d0+2)*68 + n] = v.z;
                Ks[(d0+3)*68 + n] = v.w;
            }
            #pragma unroll
            for (int i = 0; i < 8; i++) {
                int e = tid + i * 256;
                int row = e >> 5, quad = e & 31;
                float4 v = *(const float4*)(g_qkv + (size_t)(tok0 + kt + row) * QKV_OUT
                                            + (NH + NKV) * HD + hkv * HD + quad * 4);
                *(float4*)&Vs[row * 132 + quad * 4] = v;
            }
        }
        __syncthreads();

        // S = Q K^T  (4x4 microtile per thread)
        float s_acc[4][4] = {};
        #pragma unroll 8
        for (int kk = 0; kk < HD; kk++) {
            float4 qa = *(const float4*)&Qs[kk*68 + ty*4];
            float4 kb = *(const float4*)&Ks[kk*68 + tx*4];
            float ra[4] = {qa.x,qa.y,qa.z,qa.w};
            float rb[4] = {kb.x,kb.y,kb.z,kb.w};
            #pragma unroll
            for (int i = 0; i < 4; i++)
                #pragma unroll
                for (int j = 0; j < 4; j++)
                    s_acc[i][j] += ra[i] * rb[j];
        }
        const float* mrow = mask + (size_t)b * S_LEN * S_LEN
                            + (size_t)(q0 + ty*4) * S_LEN + kt + tx*4;
        #pragma unroll
        for (int i = 0; i < 4; i++)
            #pragma unroll
            for (int j = 0; j < 4; j++)
                Ps[(tx*4+j)*68 + ty*4+i] = s_acc[i][j] * scale + mrow[(size_t)i * S_LEN + j];
        __syncthreads();

        // online softmax (4 threads per row)
        {
            int r = tid >> 2, p = tid & 3;
            float mo = m_s[r];
            float mx = -1e30f;
            for (int c = p; c < BKT; c += 4) mx = fmaxf(mx, Ps[c*68 + r]);
            mx = fmaxf(mx, __shfl_xor_sync(0xffffffffu, mx, 1));
            mx = fmaxf(mx, __shfl_xor_sync(0xffffffffu, mx, 2));
            float mn = fmaxf(mo, mx);
            float sum = 0.f;
            for (int c = p; c < BKT; c += 4) {
                float e = __expf(Ps[c*68 + r] - mn);
                Ps[c*68 + r] = e;
                sum += e;
            }
            sum += __shfl_xor_sync(0xffffffffu, sum, 1);
            sum += __shfl_xor_sync(0xffffffffu, sum, 2);
            if (p == 0) {
                a_s[r] = __expf(mo - mn);
                m_s[r] = mn;
                l_s[r] = l_s[r] * a_s[r] + sum;
            }
        }
        __syncthreads();

        // rescale accumulators, then O += P V
        {
            float al[4];
            #pragma unroll
            for (int i = 0; i < 4; i++) al[i] = a_s[ty*4 + i];
            #pragma unroll
            for (int i = 0; i < 4; i++)
                #pragma unroll
                for (int j = 0; j < 8; j++) acc[i][j] *= al[i];
            #pragma unroll 4
            for (int jj = 0; jj < BKT; jj++) {
                float4 pv = *(const float4*)&Ps[jj*68 + ty*4];
                float4 v0 = *(const float4*)&Vs[jj*132 + tx*8];
                float4 v1 = *(const float4*)&Vs[jj*132 + tx*8 + 4];
                float rp[4] = {pv.x,pv.y,pv.z,pv.w};
                float rv[8] = {v0.x,v0.y,v0.z,v0.w,v1.x,v1.y,v1.z,v1.w};
                #pragma unroll
                for (int i = 0; i < 4; i++)
                    #pragma unroll
                    for (int j = 0; j < 8; j++)
                        acc[i][j] += rp[i] * rv[j];
            }
        }
    }
    __syncthreads();
    #pragma unroll
    for (int i = 0; i < 4; i++) {
        float linv = 1.0f / l_s[ty*4 + i];
        float* op = g_attn + (size_t)(tok0 + q0 + ty*4 + i) * DIMM + h*HD + tx*8;
        *(float4*)op       = make_float4(acc[i][0]*linv, acc[i][1]*linv, acc[i][2]*linv, acc[i][3]*linv);
        *(float4*)(op + 4) = make_float4(acc[i][4]*linv, acc[i][5]*linv, acc[i][6]*linv, acc[i][7]*linv);
    }
}

// ---------------- launch ----------------
extern "C" void kernel_launch(void* const* d_in, const int* in_sizes, int n_in,
                              void* d_out, int out_size)
{
    const float* x     = (const float*)d_in[0];
    const float* mask  = (const float*)d_in[1];
    const float* freqs = (const float*)d_in[2];
    const float* w_qkv = (const float*)d_in[3];
    const float* w_out = (const float*)d_in[4];
    const float* q_w   = (const float*)d_in[5];
    const float* k_w   = (const float*)d_in[6];
    float* out = (float*)d_out;

    float *qkv_p, *attn_p;
    cudaGetSymbolAddress((void**)&qkv_p,  g_qkv);
    cudaGetSymbolAddress((void**)&attn_p, g_attn);

    cudaFuncSetAttribute(flash_kernel,
                         cudaFuncAttributeMaxDynamicSharedMemorySize, FL_SMEM_BYTES);

    // 1) QKV projection: [4096,4096] = x[4096,2048] * w_qkv[4096,2048]^T
    sgemm_nt<<<dim3(QKV_OUT/128, NTOK/128), 256>>>(x, w_qkv, qkv_p, NTOK, QKV_OUT, DIMM);
    // 2) per-head RMSNorm + RoPE for q and k
    norm_rope_kernel<<<dim3(NTOK, NH + NKV), 128>>>(freqs, q_w, k_w);
    // 3) flash attention (GQA: kv head = h/2), V read straight from qkv buffer
    flash_kernel<<<dim3(S_LEN/BQ, NH, 2), 256, FL_SMEM_BYTES>>>(mask);
    // 4) output projection: out[4096,2048] = attn[4096,2048] * w_out[2048,2048]^T
    sgemm_nt<<<dim3(DIMM/128, NTOK/128), 256>>>(attn_p, w_out, out, NTOK, DIMM, DIMM);
}

// round 2
// speedup vs baseline: 1.0901x; 1.0901x over previous
#include <cuda_runtime.h>
#include <cstdint>

#define S_LEN 2048
#define DIMM  2048
#define NH    16
#define NKV   8
#define HD    128
#define NTOK  4096
#define QKV_OUT 4096
#define BQ    64
#define BKT   64

typedef unsigned long long u64;

// packed f32x2 helpers (FFMA2 path — 2x fp32 throughput on sm_103a)
__device__ __forceinline__ void fma2(u64 &d, u64 a, u64 b) {
    asm("fma.rn.f32x2 %0, %1, %2, %0;" : "+l"(d) : "l"(a), "l"(b));
}
__device__ __forceinline__ u64 mul2(u64 a, u64 b) {
    u64 d; asm("mul.rn.f32x2 %0, %1, %2;" : "=l"(d) : "l"(a), "l"(b)); return d;
}
__device__ __forceinline__ u64 pack2(float x) {
    u64 r; asm("mov.b64 %0, {%1, %1};" : "=l"(r) : "f"(x)); return r;
}

#define FL_SMEM_FLOATS (2*128*68 + 64*132 + 64*65 + 16)
#define FL_SMEM_BYTES  (FL_SMEM_FLOATS * 4)

// ---------------- scratch (static device memory; no allocation) ----------------
__device__ float g_qkv[(size_t)NTOK * QKV_OUT];   // 64 MB
__device__ float g_q[(size_t)NTOK * NH * HD];     // 32 MB
__device__ float g_k[(size_t)NTOK * NKV * HD];    // 16 MB
__device__ float g_attn[(size_t)NTOK * DIMM];     // 32 MB

// ---------------- SGEMM: C[M,N] = A[M,K] * B[N,K]^T, FFMA2 + double buffer ----------------
__global__ __launch_bounds__(256) void sgemm_nt(
    const float* __restrict__ A, const float* __restrict__ B,
    float* __restrict__ C, int M, int N, int K)
{
    __shared__ float As[2][8][128];
    __shared__ float Bs[2][8][128];
    const int tid  = threadIdx.x;
    const int tx   = tid & 15, ty = tid >> 4;
    const int lrow = tid >> 1, lk = (tid & 1) << 2;
    const float* Ag = A + (size_t)(blockIdx.y * 128 + lrow) * K + lk;
    const float* Bg = B + (size_t)(blockIdx.x * 128 + lrow) * K + lk;

    // first tile -> buffer 0
    {
        float4 a = *(const float4*)Ag;
        float4 b = *(const float4*)Bg;
        As[0][lk+0][lrow] = a.x; As[0][lk+1][lrow] = a.y;
        As[0][lk+2][lrow] = a.z; As[0][lk+3][lrow] = a.w;
        Bs[0][lk+0][lrow] = b.x; Bs[0][lk+1][lrow] = b.y;
        Bs[0][lk+2][lrow] = b.z; Bs[0][lk+3][lrow] = b.w;
    }
    __syncthreads();

    u64 acc[8][4] = {};
    const int T = K >> 3;
    for (int t = 0; t < T; t++) {
        const int cur = t & 1;
        float4 an, bn;
        if (t + 1 < T) {
            an = *(const float4*)(Ag + (t+1)*8);
            bn = *(const float4*)(Bg + (t+1)*8);
        }
        #pragma unroll
        for (int kk = 0; kk < 8; kk++) {
            float4 a0 = *(const float4*)&As[cur][kk][ty*8];
            float4 a1 = *(const float4*)&As[cur][kk][ty*8+4];
            ulonglong2 b0 = *(const ulonglong2*)&Bs[cur][kk][tx*8];
            ulonglong2 b1 = *(const ulonglong2*)&Bs[cur][kk][tx*8+4];
            u64 rb[4] = {b0.x, b0.y, b1.x, b1.y};
            float ra[8] = {a0.x,a0.y,a0.z,a0.w,a1.x,a1.y,a1.z,a1.w};
            #pragma unroll
            for (int i = 0; i < 8; i++) {
                u64 ai = pack2(ra[i]);
                #pragma unroll
                for (int j = 0; j < 4; j++) fma2(acc[i][j], ai, rb[j]);
            }
        }
        if (t + 1 < T) {
            const int nxt = cur ^ 1;
            As[nxt][lk+0][lrow] = an.x; As[nxt][lk+1][lrow] = an.y;
            As[nxt][lk+2][lrow] = an.z; As[nxt][lk+3][lrow] = an.w;
            Bs[nxt][lk+0][lrow] = bn.x; Bs[nxt][lk+1][lrow] = bn.y;
            Bs[nxt][lk+2][lrow] = bn.z; Bs[nxt][lk+3][lrow] = bn.w;
            __syncthreads();
        }
    }
    #pragma unroll
    for (int i = 0; i < 8; i++) {
        float* cp = C + (size_t)(blockIdx.y*128 + ty*8 + i) * N + blockIdx.x*128 + tx*8;
        ((ulonglong2*)cp)[0] = make_ulonglong2(acc[i][0], acc[i][1]);
        ((ulonglong2*)cp)[1] = make_ulonglong2(acc[i][2], acc[i][3]);
    }
}

// ---------------- fused per-head RMSNorm + RoPE ----------------
__global__ __launch_bounds__(128) void norm_rope_kernel(
    const float* __restrict__ freqs,  // [S,1,64,2,2]
    const float* __restrict__ qw, const float* __restrict__ kw)
{
    const int t  = blockIdx.x;
    const int hh = blockIdx.y;
    const int d  = threadIdx.x;
    const bool isq = hh < NH;
    const int h = isq ? hh : hh - NH;
    const size_t base = (size_t)t * QKV_OUT + (isq ? h*HD : NH*HD + h*HD);
    float v = g_qkv[base + d];

    float ss = v * v;
    #pragma unroll
    for (int o = 16; o; o >>= 1) ss += __shfl_xor_sync(0xffffffffu, ss, o);
    __shared__ float red[4];
    if ((d & 31) == 0) red[d >> 5] = ss;
    __syncthreads();
    ss = red[0] + red[1] + red[2] + red[3];

    float w  = isq ? qw[d] : kw[d];
    float xn = v * rsqrtf(ss * (1.0f / HD) + 1e-5f) * w;

    float other = __shfl_xor_sync(0xffffffffu, xn, 1);
    int f = d >> 1, r = d & 1;
    float x0 = (r == 0) ? xn : other;
    float x1 = (r == 0) ? other : xn;
    int s = t & (S_LEN - 1);
    const float* fc = freqs + ((size_t)s * 64 + f) * 4 + r * 2;
    float outv = fc[0] * x0 + fc[1] * x1;

    if (isq) g_q[((size_t)t * NH  + h) * HD + d] = outv;
    else     g_k[((size_t)t * NKV + h) * HD + d] = outv;
}

// ---------------- fp32 flash attention, register softmax, FFMA2 ----------------
// grid (S/BQ, NH, B), 256 threads, dynamic smem.
__global__ __launch_bounds__(256) void flash_kernel(const float* __restrict__ mask)
{
    extern __shared__ float sm[];
    float* Qs  = sm;                 // [128 d][68]  rows 0..63 used
    float* Ks  = sm + 128*68;        // [128 d][68]
    float* Vs  = sm + 2*128*68;      // [64 key][132]
    float* Ps  = Vs + 64*132;        // [64 col][65 row-stride]

    const int tid  = threadIdx.x;
    const int lane = tid & 31, w = tid >> 5;
    const int tx = tid & 15, ty = tid >> 4;
    const int h = blockIdx.y, b = blockIdx.z;
    const int hkv = h >> 1;
    const int q0 = blockIdx.x * BQ;
    const int tok0 = b * S_LEN;
    const float scale = 0.088388347762f;   // 1/sqrt(128)

    // transpose-load Q tile -> Qs[d][row]; lane==row keeps smem writes conflict-free
    {
        int n  = lane + ((w & 1) << 5);
        int qb = (w >> 1) * 8;
        const float* qr = g_q + ((size_t)(tok0 + q0 + n) * NH + h) * HD;
        #pragma unroll
        for (int i = 0; i < 8; i++) {
            int d0 = (qb + i) * 4;
            float4 v = *(const float4*)(qr + d0);
            Qs[(d0+0)*68 + n] = v.x;
            Qs[(d0+1)*68 + n] = v.y;
            Qs[(d0+2)*68 + n] = v.z;
            Qs[(d0+3)*68 + n] = v.w;
        }
    }

    float m_r[4], l_r[4];
    #pragma unroll
    for (int i = 0; i < 4; i++) { m_r[i] = -1e30f; l_r[i] = 0.f; }
    u64 acc[4][4] = {};

    for (int kt = 0; kt < S_LEN; kt += BKT) {
        __syncthreads();
        // K tile transposed, V tile natural
        {
            int n  = lane + ((w & 1) << 5);
            int qb = (w >> 1) * 8;
            const float* kr = g_k + ((size_t)(tok0 + kt + n) * NKV + hkv) * HD;
            #pragma unroll
            for (int i = 0; i < 8; i++) {
                int d0 = (qb + i) * 4;
                float4 v = *(const float4*)(kr + d0);
                Ks[(d0+0)*68 + n] = v.x;
                Ks[(d0+1)*68 + n] = v.y;
                Ks[(d0+2)*68 + n] = v.z;
                Ks[(d0+3)*68 + n] = v.w;
            }
            #pragma unroll
            for (int i = 0; i < 8; i++) {
                int e = tid + i * 256;
                int row = e >> 5, quad = e & 31;
                float4 v = *(const float4*)(g_qkv + (size_t)(tok0 + kt + row) * QKV_OUT
                                            + (NH + NKV) * HD + hkv * HD + quad * 4);
                *(float4*)&Vs[row * 132 + quad * 4] = v;
            }
        }
        __syncthreads();

        // S = Q K^T, packed accumulators (4 rows x 2 packed cols)
        u64 s2[4][2] = {};
        #pragma unroll 8
        for (int kk = 0; kk < HD; kk++) {
            float4 qa = *(const float4*)&Qs[kk*68 + ty*4];
            ulonglong2 kb = *(const ulonglong2*)&Ks[kk*68 + tx*4];
            float ra[4] = {qa.x,qa.y,qa.z,qa.w};
            #pragma unroll
            for (int i = 0; i < 4; i++) {
                u64 ai = pack2(ra[i]);
                fma2(s2[i][0], ai, kb.x);
                fma2(s2[i][1], ai, kb.y);
            }
        }

        // unpack, scale + mask
        float t[4][4];
        const float* mrow = mask + (size_t)b * S_LEN * S_LEN
                            + (size_t)(q0 + ty*4) * S_LEN + kt + tx*4;
        #pragma unroll
        for (int i = 0; i < 4; i++) {
            float lo0, hi0, lo1, hi1;
            asm("mov.b64 {%0, %1}, %2;" : "=f"(lo0), "=f"(hi0) : "l"(s2[i][0]));
            asm("mov.b64 {%0, %1}, %2;" : "=f"(lo1), "=f"(hi1) : "l"(s2[i][1]));
            float4 mv = *(const float4*)(mrow + (size_t)i * S_LEN);
            t[i][0] = lo0 * scale + mv.x;
            t[i][1] = hi0 * scale + mv.y;
            t[i][2] = lo1 * scale + mv.z;
            t[i][3] = hi1 * scale + mv.w;
        }

        // register softmax: reduce across the 16 tx-lanes (half-warp) per row
        float aa[4];
        #pragma unroll
        for (int i = 0; i < 4; i++) {
            float mx = fmaxf(fmaxf(t[i][0], t[i][1]), fmaxf(t[i][2], t[i][3]));
            #pragma unroll
            for (int o = 1; o < 16; o <<= 1)
                mx = fmaxf(mx, __shfl_xor_sync(0xffffffffu, mx, o));
            float mn = fmaxf(m_r[i], mx);
            aa[i] = __expf(m_r[i] - mn);
            m_r[i] = mn;
            float sum = 0.f;
            #pragma unroll
            for (int j = 0; j < 4; j++) {
                t[i][j] = __expf(t[i][j] - mn);
                sum += t[i][j];
            }
            #pragma unroll
            for (int o = 1; o < 16; o <<= 1)
                sum += __shfl_xor_sync(0xffffffffu, sum, o);
            l_r[i] = l_r[i] * aa[i] + sum;
        }

        // store exponentiated P transposed: Ps[col][row], stride 65 (odd -> <=2-way)
        #pragma unroll
        for (int j = 0; j < 4; j++)
            #pragma unroll
            for (int i = 0; i < 4; i++)
                Ps[(tx*4+j)*65 + ty*4 + i] = t[i][j];
        __syncthreads();

        // rescale accumulators then O += P V (packed)
        #pragma unroll
        for (int i = 0; i < 4; i++) {
            u64 av = pack2(aa[i]);
            #pragma unroll
            for (int j = 0; j < 4; j++) acc[i][j] = mul2(acc[i][j], av);
        }
        #pragma unroll 4
        for (int jj = 0; jj < BKT; jj++) {
            ulonglong2 v0 = *(const ulonglong2*)&Vs[jj*132 + tx*8];
            ulonglong2 v1 = *(const ulonglong2*)&Vs[jj*132 + tx*8 + 4];
            u64 rv[4] = {v0.x, v0.y, v1.x, v1.y};
            #pragma unroll
            for (int i = 0; i < 4; i++) {
                u64 pi = pack2(Ps[jj*65 + ty*4 + i]);
                #pragma unroll
                for (int j = 0; j < 4; j++) fma2(acc[i][j], pi, rv[j]);
            }
        }
    }

    #pragma unroll
    for (int i = 0; i < 4; i++) {
        u64 lv = pack2(1.0f / l_r[i]);
        float* op = g_attn + (size_t)(tok0 + q0 + ty*4 + i) * DIMM + h*HD + tx*8;
        ((ulonglong2*)op)[0] = make_ulonglong2(mul2(acc[i][0], lv), mul2(acc[i][1], lv));
        ((ulonglong2*)op)[1] = make_ulonglong2(mul2(acc[i][2], lv), mul2(acc[i][3], lv));
    }
}

// ---------------- launch ----------------
extern "C" void kernel_launch(void* const* d_in, const int* in_sizes, int n_in,
                              void* d_out, int out_size)
{
    const float* x     = (const float*)d_in[0];
    const float* mask  = (const float*)d_in[1];
    const float* freqs = (const float*)d_in[2];
    const float* w_qkv = (const float*)d_in[3];
    const float* w_out = (const float*)d_in[4];
    const float* q_w   = (const float*)d_in[5];
    const float* k_w   = (const float*)d_in[6];
    float* out = (float*)d_out;

    float *qkv_p, *attn_p;
    cudaGetSymbolAddress((void**)&qkv_p,  g_qkv);
    cudaGetSymbolAddress((void**)&attn_p, g_attn);

    cudaFuncSetAttribute(flash_kernel,
                         cudaFuncAttributeMaxDynamicSharedMemorySize, FL_SMEM_BYTES);

    sgemm_nt<<<dim3(QKV_OUT/128, NTOK/128), 256>>>(x, w_qkv, qkv_p, NTOK, QKV_OUT, DIMM);
    norm_rope_kernel<<<dim3(NTOK, NH + NKV), 128>>>(freqs, q_w, k_w);
    flash_kernel<<<dim3(S_LEN/BQ, NH, 2), 256, FL_SMEM_BYTES>>>(mask);
    sgemm_nt<<<dim3(DIMM/128, NTOK/128), 256>>>(attn_p, w_out, out, NTOK, DIMM, DIMM);
}

// round 4
// speedup vs baseline: 1.4592x; 1.3386x over previous
#include <cuda_runtime.h>
#include <cstdint>

#define S_LEN 2048
#define DIMM  2048
#define NH    16
#define NKV   8
#define HD    128
#define NTOK  4096
#define QKV_OUT 4096
#define BQ    64
#define BKT   64

typedef unsigned long long u64;
typedef unsigned int u32;

// ---------------- helpers ----------------
__device__ __forceinline__ u32 f2tf(float x) {
    u32 r; asm("cvt.rna.tf32.f32 %0, %1;" : "=r"(r) : "f"(x)); return r;
}
__device__ __forceinline__ void mma8(float* d, const u32* a, const u32* b) {
    asm volatile("mma.sync.aligned.m16n8k8.row.col.f32.tf32.tf32.f32 "
        "{%0,%1,%2,%3}, {%4,%5,%6,%7}, {%8,%9}, {%0,%1,%2,%3};"
        : "+f"(d[0]), "+f"(d[1]), "+f"(d[2]), "+f"(d[3])
        : "r"(a[0]), "r"(a[1]), "r"(a[2]), "r"(a[3]), "r"(b[0]), "r"(b[1]));
}
__device__ __forceinline__ float sel4(float a, float b, float c, float d, int s) {
    float lo = (s & 1) ? b : a;
    float hi = (s & 1) ? d : c;
    return (s & 2) ? hi : lo;
}
// packed f32x2 helpers (flash kernel)
__device__ __forceinline__ void fma2(u64 &d, u64 a, u64 b) {
    asm("fma.rn.f32x2 %0, %1, %2, %0;" : "+l"(d) : "l"(a), "l"(b));
}
__device__ __forceinline__ u64 mul2(u64 a, u64 b) {
    u64 d; asm("mul.rn.f32x2 %0, %1, %2;" : "=l"(d) : "l"(a), "l"(b)); return d;
}
__device__ __forceinline__ u64 pack2(float x) {
    u64 r; asm("mov.b64 %0, {%1, %1};" : "=l"(r) : "f"(x)); return r;
}

// ---------------- scratch ----------------
__device__ float g_qkv[(size_t)NTOK * QKV_OUT];
__device__ float g_q[(size_t)NTOK * NH * HD];
__device__ float g_k[(size_t)NTOK * NKV * HD];
__device__ float g_attn[(size_t)NTOK * DIMM];

// ---------------- tf32 mma.sync GEMM: C[M,N] = A[M,K] * B[N,K]^T ----------------
// CTA 128x128, 8 warps of 64x32, K staged 16, double-buffered smem (frag-major).
__global__ __launch_bounds__(256, 2) void gemm_mma(
    const float* __restrict__ A, const float* __restrict__ B,
    float* __restrict__ C, int M, int N, int K)
{
    __shared__ u32 sm[8192];  // 2 bufs x (A 2048 + B 2048) u32
    const int tid = threadIdx.x, w = tid >> 5, L = tid & 31;
    const int m0 = blockIdx.y * 128, n0 = blockIdx.x * 128;

    // writer A lane decode: bank bijection (g&1, cl, ch, half)
    const int a_gb = (L >> 4) & 1, a_ch = (L >> 3) & 1, a_half = (L >> 2) & 1, a_gp = L & 3;
    const int a_g  = a_gp * 2 + a_gb;
    const int a_r  = w * 16 + a_half * 8 + a_g;
    const int a_reg = a_half + 2 * a_ch;
    // writer B lane decode
    const int b_n8 = ((L & 1) << 2) | ((L >> 3) & 3);
    const int b_ch = (L >> 2) & 1;
    const int b_nt = w * 2 + ((L >> 1) & 1);
    const int b_r  = b_nt * 8 + b_n8;

    const float* Ag = A + (size_t)(m0 + a_r) * K + a_ch * 4;
    const float* Bg = B + (size_t)(n0 + b_r) * K + b_ch * 4;

    const int mw = w & 1, nq = w >> 1;

    float acc[4][4][4];
    #pragma unroll
    for (int i = 0; i < 4; i++)
        #pragma unroll
        for (int j = 0; j < 4; j++)
            #pragma unroll
            for (int q = 0; q < 4; q++) acc[i][j][q] = 0.f;

    const int S = K >> 4;
    float4 pa[2], pb[2];
    pa[0] = *(const float4*)(Ag);     pa[1] = *(const float4*)(Ag + 8);
    pb[0] = *(const float4*)(Bg);     pb[1] = *(const float4*)(Bg + 8);

    for (int s = 0; s < S; s++) {
        u32* smc = sm + (s & 1) * 4096;
        // ---- STS stage s (frag-major, rotated for conflict-free banks) ----
        #pragma unroll
        for (int i = 0; i < 2; i++) {
            const u32 abase = (u32)((w * 2 + i) * 128 + a_g * 16 + a_reg);
            const u32 bbase = (u32)(2048 + (b_nt * 2 + i) * 64 + b_n8 * 8 + b_ch);
            float4 va = pa[i], vb = pb[i];
            #pragma unroll
            for (int j = 0; j < 4; j++) {
                int cl = (j + L) & 3;
                smc[abase + cl * 4] = f2tf(sel4(va.x, va.y, va.z, va.w, cl));
            }
            #pragma unroll
            for (int j = 0; j < 4; j++) {
                int cl = (j + L) & 3;
                smc[bbase + cl * 2] = f2tf(sel4(vb.x, vb.y, vb.z, vb.w, cl));
            }
        }
        __syncthreads();
        // ---- prefetch stage s+1 ----
        if (s + 1 < S) {
            const float* Ag2 = Ag + (s + 1) * 16;
            const float* Bg2 = Bg + (s + 1) * 16;
            pa[0] = *(const float4*)(Ag2);     pa[1] = *(const float4*)(Ag2 + 8);
            pb[0] = *(const float4*)(Bg2);     pb[1] = *(const float4*)(Bg2 + 8);
        }
        // ---- compute 2 k8 steps ----
        #pragma unroll
        for (int kk = 0; kk < 2; kk++) {
            u32 af[4][4]; u32 bf[4][2];
            #pragma unroll
            for (int mt = 0; mt < 4; mt++) {
                uint4 t = *(const uint4*)&smc[(((mw * 4 + mt) * 2 + kk) * 128) + L * 4];
                af[mt][0] = t.x; af[mt][1] = t.y; af[mt][2] = t.z; af[mt][3] = t.w;
            }
            #pragma unroll
            for (int nt = 0; nt < 4; nt++) {
                uint2 t = *(const uint2*)&smc[2048 + ((nq * 4 + nt) * 2 + kk) * 64 + L * 2];
                bf[nt][0] = t.x; bf[nt][1] = t.y;
            }
            #pragma unroll
            for (int mt = 0; mt < 4; mt++)
                #pragma unroll
                for (int nt = 0; nt < 4; nt++)
                    mma8(acc[mt][nt], af[mt], bf[nt]);
        }
        __syncthreads();
    }

    // ---- epilogue ----
    #pragma unroll
    for (int mt = 0; mt < 4; mt++) {
        const int r0 = m0 + mw * 64 + mt * 16 + (L >> 2);
        #pragma unroll
        for (int nt = 0; nt < 4; nt++) {
            const int c0 = n0 + nq * 32 + nt * 8 + (L & 3) * 2;
            float* p0 = C + (size_t)r0 * N + c0;
            float* p1 = C + (size_t)(r0 + 8) * N + c0;
            *(float2*)p0 = make_float2(acc[mt][nt][0], acc[mt][nt][1]);
            *(float2*)p1 = make_float2(acc[mt][nt][2], acc[mt][nt][3]);
        }
    }
}

// ---------------- fused per-head RMSNorm + RoPE ----------------
__global__ __launch_bounds__(128) void norm_rope_kernel(
    const float* __restrict__ freqs,
    const float* __restrict__ qw, const float* __restrict__ kw)
{
    const int t  = blockIdx.x;
    const int hh = blockIdx.y;
    const int d  = threadIdx.x;
    const bool isq = hh < NH;
    const int h = isq ? hh : hh - NH;
    const size_t base = (size_t)t * QKV_OUT + (isq ? h*HD : NH*HD + h*HD);
    float v = g_qkv[base + d];

    float ss = v * v;
    #pragma unroll
    for (int o = 16; o; o >>= 1) ss += __shfl_xor_sync(0xffffffffu, ss, o);
    __shared__ float red[4];
    if ((d & 31) == 0) red[d >> 5] = ss;
    __syncthreads();
    ss = red[0] + red[1] + red[2] + red[3];

    float w  = isq ? qw[d] : kw[d];
    float xn = v * rsqrtf(ss * (1.0f / HD) + 1e-5f) * w;

    float other = __shfl_xor_sync(0xffffffffu, xn, 1);
    int f = d >> 1, r = d & 1;
    float x0 = (r == 0) ? xn : other;
    float x1 = (r == 0) ? other : xn;
    int s = t & (S_LEN - 1);
    const float* fc = freqs + ((size_t)s * 64 + f) * 4 + r * 2;
    float outv = fc[0] * x0 + fc[1] * x1;

    if (isq) g_q[((size_t)t * NH  + h) * HD + d] = outv;
    else     g_k[((size_t)t * NKV + h) * HD + d] = outv;
}

// ---------------- fp32 flash attention (register softmax, FFMA2) ----------------
#define FL_SMEM_FLOATS (2*128*68 + 64*132 + 64*65 + 16)
#define FL_SMEM_BYTES  (FL_SMEM_FLOATS * 4)

__global__ __launch_bounds__(256) void flash_kernel(const float* __restrict__ mask)
{
    extern __shared__ float sm[];
    float* Qs  = sm;
    float* Ks  = sm + 128*68;
    float* Vs  = sm + 2*128*68;
    float* Ps  = Vs + 64*132;

    const int tid  = threadIdx.x;
    const int lane = tid & 31, w = tid >> 5;
    const int tx = tid & 15, ty = tid >> 4;
    const int h = blockIdx.y, b = blockIdx.z;
    const int hkv = h >> 1;
    const int q0 = blockIdx.x * BQ;
    const int tok0 = b * S_LEN;
    const float scale = 0.088388347762f;

    {
        int n  = lane + ((w & 1) << 5);
        int qb = (w >> 1) * 8;
        const float* qr = g_q + ((size_t)(tok0 + q0 + n) * NH + h) * HD;
        #pragma unroll
        for (int i = 0; i < 8; i++) {
            int d0 = (qb + i) * 4;
            float4 v = *(const float4*)(qr + d0);
            Qs[(d0+0)*68 + n] = v.x;
            Qs[(d0+1)*68 + n] = v.y;
            Qs[(d0+2)*68 + n] = v.z;
            Qs[(d0+3)*68 + n] = v.w;
        }
    }

    float m_r[4], l_r[4];
    #pragma unroll
    for (int i = 0; i < 4; i++) { m_r[i] = -1e30f; l_r[i] = 0.f; }
    u64 acc[4][4] = {};

    for (int kt = 0; kt < S_LEN; kt += BKT) {
        __syncthreads();
        {
            int n  = lane + ((w & 1) << 5);
            int qb = (w >> 1) * 8;
            const float* kr = g_k + ((size_t)(tok0 + kt + n) * NKV + hkv) * HD;
            #pragma unroll
            for (int i = 0; i < 8; i++) {
                int d0 = (qb + i) * 4;
                float4 v = *(const float4*)(kr + d0);
                Ks[(d0+0)*68 + n] = v.x;
                Ks[(d0+1)*68 + n] = v.y;
                Ks[(d0+2)*68 + n] = v.z;
                Ks[(d0+3)*68 + n] = v.w;
            }
            #pragma unroll
            for (int i = 0; i < 8; i++) {
                int e = tid + i * 256;
                int row = e >> 5, quad = e & 31;
                float4 v = *(const float4*)(g_qkv + (size_t)(tok0 + kt + row) * QKV_OUT
                                            + (NH + NKV) * HD + hkv * HD + quad * 4);
                *(float4*)&Vs[row * 132 + quad * 4] = v;
            }
        }
        __syncthreads();

        u64 s2[4][2] = {};
        #pragma unroll 8
        for (int kk = 0; kk < HD; kk++) {
            float4 qa = *(const float4*)&Qs[kk*68 + ty*4];
            ulonglong2 kb = *(const ulonglong2*)&Ks[kk*68 + tx*4];
            float ra[4] = {qa.x,qa.y,qa.z,qa.w};
            #pragma unroll
            for (int i = 0; i < 4; i++) {
                u64 ai = pack2(ra[i]);
                fma2(s2[i][0], ai, kb.x);
                fma2(s2[i][1], ai, kb.y);
            }
        }

        float t[4][4];
        const float* mrow = mask + (size_t)b * S_LEN * S_LEN
                            + (size_t)(q0 + ty*4) * S_LEN + kt + tx*4;
        #pragma unroll
        for (int i = 0; i < 4; i++) {
            float lo0, hi0, lo1, hi1;
            asm("mov.b64 {%0, %1}, %2;" : "=f"(lo0), "=f"(hi0) : "l"(s2[i][0]));
            asm("mov.b64 {%0, %1}, %2;" : "=f"(lo1), "=f"(hi1) : "l"(s2[i][1]));
            float4 mv = *(const float4*)(mrow + (size_t)i * S_LEN);
            t[i][0] = lo0 * scale + mv.x;
            t[i][1] = hi0 * scale + mv.y;
            t[i][2] = lo1 * scale + mv.z;
            t[i][3] = hi1 * scale + mv.w;
        }

        float aa[4];
        #pragma unroll
        for (int i = 0; i < 4; i++) {
            float mx = fmaxf(fmaxf(t[i][0], t[i][1]), fmaxf(t[i][2], t[i][3]));
            #pragma unroll
            for (int o = 1; o < 16; o <<= 1)
                mx = fmaxf(mx, __shfl_xor_sync(0xffffffffu, mx, o));
            float mn = fmaxf(m_r[i], mx);
            aa[i] = __expf(m_r[i] - mn);
            m_r[i] = mn;
            float sum = 0.f;
            #pragma unroll
            for (int j = 0; j < 4; j++) {
                t[i][j] = __expf(t[i][j] - mn);
                sum += t[i][j];
            }
            #pragma unroll
            for (int o = 1; o < 16; o <<= 1)
                sum += __shfl_xor_sync(0xffffffffu, sum, o);
            l_r[i] = l_r[i] * aa[i] + sum;
        }

        #pragma unroll
        for (int j = 0; j < 4; j++)
            #pragma unroll
            for (int i = 0; i < 4; i++)
                Ps[(tx*4+j)*65 + ty*4 + i] = t[i][j];
        __syncthreads();

        #pragma unroll
        for (int i = 0; i < 4; i++) {
            u64 av = pack2(aa[i]);
            #pragma unroll
            for (int j = 0; j < 4; j++) acc[i][j] = mul2(acc[i][j], av);
        }
        #pragma unroll 4
        for (int jj = 0; jj < BKT; jj++) {
            ulonglong2 v0 = *(const ulonglong2*)&Vs[jj*132 + tx*8];
            ulonglong2 v1 = *(const ulonglong2*)&Vs[jj*132 + tx*8 + 4];
            u64 rv[4] = {v0.x, v0.y, v1.x, v1.y};
            #pragma unroll
            for (int i = 0; i < 4; i++) {
                u64 pi = pack2(Ps[jj*65 + ty*4 + i]);
                #pragma unroll
                for (int j = 0; j < 4; j++) fma2(acc[i][j], pi, rv[j]);
            }
        }
    }

    #pragma unroll
    for (int i = 0; i < 4; i++) {
        u64 lv = pack2(1.0f / l_r[i]);
        float* op = g_attn + (size_t)(tok0 + q0 + ty*4 + i) * DIMM + h*HD + tx*8;
        ((ulonglong2*)op)[0] = make_ulonglong2(mul2(acc[i][0], lv), mul2(acc[i][1], lv));
        ((ulonglong2*)op)[1] = make_ulonglong2(mul2(acc[i][2], lv), mul2(acc[i][3], lv));
    }
}

// ---------------- launch ----------------
extern "C" void kernel_launch(void* const* d_in, const int* in_sizes, int n_in,
                              void* d_out, int out_size)
{
    const float* x     = (const float*)d_in[0];
    const float* mask  = (const float*)d_in[1];
    const float* freqs = (const float*)d_in[2];
    const float* w_qkv = (const float*)d_in[3];
    const float* w_out = (const float*)d_in[4];
    const float* q_w   = (const float*)d_in[5];
    const float* k_w   = (const float*)d_in[6];
    float* out = (float*)d_out;

    float *qkv_p, *attn_p;
    cudaGetSymbolAddress((void**)&qkv_p,  g_qkv);
    cudaGetSymbolAddress((void**)&attn_p, g_attn);

    cudaFuncSetAttribute(flash_kernel, cudaFuncAttributeMaxDynamicSharedMemorySize, FL_SMEM_BYTES);

    // QKV projection (tf32 tensor cores): [4096,4096] = x[4096,2048] * w_qkv^T
    gemm_mma<<<dim3(QKV_OUT/128, NTOK/128), 256>>>(x, w_qkv, qkv_p, NTOK, QKV_OUT, DIMM);
    norm_rope_kernel<<<dim3(NTOK, NH + NKV), 128>>>(freqs, q_w, k_w);
    flash_kernel<<<dim3(S_LEN/BQ, NH, 2), 256, FL_SMEM_BYTES>>>(mask);
    // out projection: [4096,2048] = attn[4096,2048] * w_out^T
    gemm_mma<<<dim3(DIMM/128, NTOK/128), 256>>>(attn_p, w_out, out, NTOK, DIMM, DIMM);
}